// round 11
// baseline (speedup 1.0000x reference)
#include <cuda_runtime.h>
#include <math.h>

#define NV 2
#define NB 16384
#define NC 100
#define ND 512
#define NBLOCKS 148
#define THREADS 512
#define WARPS 16
#define BLOCKS_PER_V (NBLOCKS / 2)            // 74
#define WARPS_PER_V (BLOCKS_PER_V * WARPS)    // 1184
#define QUADS (NB / 4)                        // 4096 quads (4 rows each) per v
#define TABLE_FLOATS (NC * ND)                // 51200 floats = 200 KB
#define MARGIN_F 10.0f

// Scratch (no dynamic allocation allowed)
__device__ float g_partials[NBLOCKS];         // per-block diff^2 partial sums
__device__ float g_inter[NV];                 // per-v inter_loss

__global__ void __launch_bounds__(THREADS) anchor_loss_main(
    const float* __restrict__ feat,
    const int* __restrict__ label,            // int32 (JAX x64 disabled)
    const float* __restrict__ anchor,
    float* __restrict__ out)                  // out[0]=loss, out[1..]=sims
{
    extern __shared__ float cs[];             // center table for this block's v (200 KB)
    const int v    = blockIdx.x & 1;
    const int bin  = blockIdx.x >> 1;         // block index within v: 0..73
    const int tid  = threadIdx.x;
    const int warp = tid >> 5;
    const int lane = tid & 31;

    // ---- stage anchor[v] table into SMEM (coalesced float4) ----
    {
        const float4* a4 = reinterpret_cast<const float4*>(anchor) + (size_t)v * (TABLE_FLOATS / 4);
        float4* s4 = reinterpret_cast<float4*>(cs);
        #pragma unroll
        for (int i = 0; i < TABLE_FLOATS / 4 / THREADS; i++)   // 25 iters
            s4[tid + THREADS * i] = a4[tid + THREADS * i];
    }
    __syncthreads();

    // ---- main loop: each warp strides over quads (4 rows per iteration) ----
    float dsum = 0.f;
    const int wv = bin * WARPS + warp;        // 0..1183 within v
    const float4* cs4 = reinterpret_cast<const float4*>(cs);

    for (int q = wv; q < QUADS; q += WARPS_PER_V) {
        const int rbase = q * 4;              // row within v

        float dt[4], fn[4], cn[4];
        const float4* ff[4];
        const float4* cc[4];
        #pragma unroll
        for (int j = 0; j < 4; j++) {
            int l = __ldg(&label[rbase + j]); // uniform across warp -> 1 request
            l = min(max(l, 0), NC - 1);
            cc[j] = cs4 + l * (ND / 4);       // SMEM: 29-cycle reads, no gather chain
            ff[j] = reinterpret_cast<const float4*>(feat)
                    + ((size_t)v * NB + rbase + j) * (ND / 4);
            dt[j] = 0.f; fn[j] = 0.f; cn[j] = 0.f;
        }

        #pragma unroll
        for (int k = 0; k < 4; k++) {
            #pragma unroll
            for (int j = 0; j < 4; j++) {
                float4 f = ff[j][lane + 32 * k];
                float4 c = cc[j][lane + 32 * k];
                dt[j] = fmaf(f.x, c.x, fmaf(f.y, c.y, fmaf(f.z, c.z, fmaf(f.w, c.w, dt[j]))));
                fn[j] = fmaf(f.x, f.x, fmaf(f.y, f.y, fmaf(f.z, f.z, fmaf(f.w, f.w, fn[j]))));
                cn[j] = fmaf(c.x, c.x, fmaf(c.y, c.y, fmaf(c.z, c.z, fmaf(c.w, c.w, cn[j]))));
            }
        }
        #pragma unroll
        for (int off = 16; off > 0; off >>= 1) {
            #pragma unroll
            for (int j = 0; j < 4; j++) {
                dt[j] += __shfl_xor_sync(0xffffffffu, dt[j], off);
                fn[j] += __shfl_xor_sync(0xffffffffu, fn[j], off);
                cn[j] += __shfl_xor_sync(0xffffffffu, cn[j], off);
            }
        }
        if (lane == 0) {
            #pragma unroll
            for (int j = 0; j < 4; j++) {
                float den = fmaxf(sqrtf(fn[j]), 1e-8f) * fmaxf(sqrtf(cn[j]), 1e-8f);
                out[1 + v * NB + rbase + j] = dt[j] / den;
                dsum += fn[j] - 2.f * dt[j] + cn[j];    // ||f-c||^2
            }
        }
    }

    // ---- block reduce of dsum ----
    __shared__ float sh[WARPS];
    if (lane == 0) sh[warp] = dsum;
    __syncthreads();
    if (tid == 0) {
        float t = 0.f;
        #pragma unroll
        for (int w = 0; w < WARPS; w++) t += sh[w];
        g_partials[blockIdx.x] = t;
    }

    // ---- blocks 0,1: inter-loss stats from the already-staged SMEM table ----
    // pair_sum = C * sum_c ||a_c||^2 - ||sum_c a_c||^2 (pd diagonal is 0)
    if (blockIdx.x < 2) {
        float m = 0.f, s = 0.f;
        #pragma unroll 4
        for (int c = 0; c < NC; c++) {
            float x = cs[c * ND + tid];       // tid = d index (512 == ND)
            m += x;
            s = fmaf(x, x, s);
        }
        float qq = m * m;

        __shared__ float shs[THREADS], shq[THREADS];
        shs[tid] = s; shq[tid] = qq;
        __syncthreads();
        #pragma unroll
        for (int off = 256; off > 0; off >>= 1) {
            if (tid < off) { shs[tid] += shs[tid + off]; shq[tid] += shq[tid + off]; }
            __syncthreads();
        }
        if (tid == 0) {
            float S  = shs[0];                // sum_c ||a_c||^2
            float M2 = shq[0];                // ||sum_c a_c||^2
            float inter = (NC * S - M2) / (float)(NC * (NC - 1));
            g_inter[v] = fmaxf(MARGIN_F - inter, 0.0f);
        }
    }
}

__global__ void __launch_bounds__(256) anchor_loss_finalize(float* __restrict__ out)
{
    const int t = threadIdx.x;                // 256 threads; 148 partials
    float p = (t < NBLOCKS) ? g_partials[t] : 0.f;
    __shared__ float s0[256];
    s0[t] = p;
    __syncthreads();
    #pragma unroll
    for (int off = 128; off > 0; off >>= 1) {
        if (t < off) s0[t] += s0[t + off];
        __syncthreads();
    }
    if (t == 0) {
        float center_mean = s0[0] / (2.0f * (float)NV * (float)NB);
        float inter_mean  = (g_inter[0] + g_inter[1]) / (float)NV;
        out[0] = center_mean + inter_mean;
    }
}

extern "C" void kernel_launch(void* const* d_in, const int* in_sizes, int n_in,
                              void* d_out, int out_size)
{
    const float* feat   = (const float*)d_in[0];
    const int*   label  = (const int*)d_in[1];
    const float* anchor = (const float*)d_in[2];
    float* out = (float*)d_out;

    static int smem_set = 0;
    const int table_bytes = TABLE_FLOATS * (int)sizeof(float);   // 204800
    if (!smem_set) {
        cudaFuncSetAttribute(anchor_loss_main,
                             cudaFuncAttributeMaxDynamicSharedMemorySize, table_bytes);
        smem_set = 1;
    }

    anchor_loss_main<<<NBLOCKS, THREADS, table_bytes>>>(feat, label, anchor, out);
    anchor_loss_finalize<<<1, 256>>>(out);
}

// round 12
// speedup vs baseline: 1.1081x; 1.1081x over previous
#include <cuda_runtime.h>
#include <math.h>

#define NV 2
#define NB 16384
#define NC 100
#define ND 512
#define ROWS_PER_WARP 2
#define WARPS_PER_BLOCK 16
#define ROWS_PER_BLOCK (WARPS_PER_BLOCK * ROWS_PER_WARP)   // 32
#define BLOCKS_PER_V (NB / ROWS_PER_BLOCK)                 // 512
#define MAIN_BLOCKS (NV * BLOCKS_PER_V)                    // 1024
#define MARGIN_F 10.0f

// Scratch (no dynamic allocation allowed)
__device__ float g_partials[MAIN_BLOCKS];        // per-block diff^2 partial sums
__device__ float g_inter[NV];                    // per-v inter_loss

// Streaming load: do NOT allocate in L1 — keeps the center table L1-resident.
__device__ __forceinline__ float4 ldg_noL1(const float4* p) {
    float4 r;
    asm volatile("ld.global.L1::no_allocate.v4.f32 {%0,%1,%2,%3}, [%4];"
                 : "=f"(r.x), "=f"(r.y), "=f"(r.z), "=f"(r.w) : "l"(p));
    return r;
}

__global__ void __launch_bounds__(512) anchor_loss_main(
    const float* __restrict__ feat,
    const int* __restrict__ label,               // int32 (JAX x64 disabled)
    const float* __restrict__ anchor,
    float* __restrict__ out)                     // out[0]=loss, out[1..]=sims
{
    if (blockIdx.x < MAIN_BLOCKS) {
        // ---- main pass: 2 rows per warp (independent chains for MLP) ----
        const int warp = threadIdx.x >> 5;
        const int lane = threadIdx.x & 31;
        const int r0   = blockIdx.x * ROWS_PER_BLOCK + warp * ROWS_PER_WARP;
        const int r1   = r0 + 1;
        const int v    = r0 >> 14;
        const int b0   = r0 & (NB - 1);
        const int b1   = r1 & (NB - 1);

        const float4* f4a = reinterpret_cast<const float4*>(feat) + (size_t)r0 * (ND / 4);
        const float4* f4b = reinterpret_cast<const float4*>(feat) + (size_t)r1 * (ND / 4);
        int l0 = min(max(__ldg(&label[b0]), 0), NC - 1);
        int l1 = min(max(__ldg(&label[b1]), 0), NC - 1);
        const float4* c4a = reinterpret_cast<const float4*>(anchor)
                            + ((size_t)v * NC + l0) * (ND / 4);
        const float4* c4b = reinterpret_cast<const float4*>(anchor)
                            + ((size_t)v * NC + l1) * (ND / 4);

        float dt0 = 0.f, fn0 = 0.f, cn0 = 0.f;
        float dt1 = 0.f, fn1 = 0.f, cn1 = 0.f;
        #pragma unroll
        for (int k = 0; k < 4; k++) {
            float4 f0 = ldg_noL1(&f4a[lane + 32 * k]);   // stream: bypass L1 alloc
            float4 f1 = ldg_noL1(&f4b[lane + 32 * k]);
            float4 c0 = c4a[lane + 32 * k];              // hot: L1-resident
            float4 c1 = c4b[lane + 32 * k];
            dt0 = fmaf(f0.x, c0.x, fmaf(f0.y, c0.y, fmaf(f0.z, c0.z, fmaf(f0.w, c0.w, dt0))));
            fn0 = fmaf(f0.x, f0.x, fmaf(f0.y, f0.y, fmaf(f0.z, f0.z, fmaf(f0.w, f0.w, fn0))));
            cn0 = fmaf(c0.x, c0.x, fmaf(c0.y, c0.y, fmaf(c0.z, c0.z, fmaf(c0.w, c0.w, cn0))));
            dt1 = fmaf(f1.x, c1.x, fmaf(f1.y, c1.y, fmaf(f1.z, c1.z, fmaf(f1.w, c1.w, dt1))));
            fn1 = fmaf(f1.x, f1.x, fmaf(f1.y, f1.y, fmaf(f1.z, f1.z, fmaf(f1.w, f1.w, fn1))));
            cn1 = fmaf(c1.x, c1.x, fmaf(c1.y, c1.y, fmaf(c1.z, c1.z, fmaf(c1.w, c1.w, cn1))));
        }
        #pragma unroll
        for (int off = 16; off > 0; off >>= 1) {
            dt0 += __shfl_xor_sync(0xffffffffu, dt0, off);
            fn0 += __shfl_xor_sync(0xffffffffu, fn0, off);
            cn0 += __shfl_xor_sync(0xffffffffu, cn0, off);
            dt1 += __shfl_xor_sync(0xffffffffu, dt1, off);
            fn1 += __shfl_xor_sync(0xffffffffu, fn1, off);
            cn1 += __shfl_xor_sync(0xffffffffu, cn1, off);
        }

        __shared__ float sh[WARPS_PER_BLOCK];
        if (lane == 0) {
            float d0 = fmaxf(sqrtf(fn0), 1e-8f) * fmaxf(sqrtf(cn0), 1e-8f);
            float d1 = fmaxf(sqrtf(fn1), 1e-8f) * fmaxf(sqrtf(cn1), 1e-8f);
            __stcs(&out[1 + r0], dt0 / d0);
            __stcs(&out[1 + r1], dt1 / d1);
            // sum of squared diffs: ||f||^2 - 2 f.c + ||c||^2  (both rows)
            sh[warp] = (fn0 - 2.f * dt0 + cn0) + (fn1 - 2.f * dt1 + cn1);
        }
        __syncthreads();
        if (threadIdx.x == 0) {
            float t = 0.f;
            #pragma unroll
            for (int w = 0; w < WARPS_PER_BLOCK; w++) t += sh[w];
            g_partials[blockIdx.x] = t;
        }
    } else {
        // ---- anchor stats: one block per v (512 threads = one per d) ----
        // pair_sum = C * sum_c ||a_c||^2 - ||sum_c a_c||^2 (pd diagonal is 0)
        const int v = blockIdx.x - MAIN_BLOCKS;
        const int t = threadIdx.x;          // 0..511 = d index
        const float* a = anchor + (size_t)v * NC * ND;

        float m = 0.f, s = 0.f;
        #pragma unroll 4
        for (int c = 0; c < NC; c++) {
            float x = a[(size_t)c * ND + t];
            m += x;
            s = fmaf(x, x, s);
        }
        float q = m * m;

        __shared__ float shs[512], shq[512];
        shs[t] = s; shq[t] = q;
        __syncthreads();
        #pragma unroll
        for (int off = 256; off > 0; off >>= 1) {
            if (t < off) { shs[t] += shs[t + off]; shq[t] += shq[t + off]; }
            __syncthreads();
        }
        if (t == 0) {
            float S = shs[0];          // sum_c ||a_c||^2
            float M2 = shq[0];         // ||sum_c a_c||^2
            float inter = (NC * S - M2) / (float)(NC * (NC - 1));
            g_inter[v] = fmaxf(MARGIN_F - inter, 0.0f);
        }
    }
}

__global__ void __launch_bounds__(256) anchor_loss_finalize(float* __restrict__ out)
{
    const int t = threadIdx.x;  // 256 threads; 512 partials per v
    float t0 = g_partials[t] + g_partials[t + 256];                               // v = 0
    float t1 = g_partials[BLOCKS_PER_V + t] + g_partials[BLOCKS_PER_V + t + 256]; // v = 1

    __shared__ float s0[256], s1[256];
    s0[t] = t0; s1[t] = t1;
    __syncthreads();
    #pragma unroll
    for (int off = 128; off > 0; off >>= 1) {
        if (t < off) { s0[t] += s0[t + off]; s1[t] += s1[t + off]; }
        __syncthreads();
    }
    if (t == 0) {
        float center_mean = (s0[0] + s1[0]) / (2.0f * (float)NV * (float)NB);
        float inter_mean  = (g_inter[0] + g_inter[1]) / (float)NV;
        out[0] = center_mean + inter_mean;
    }
}

extern "C" void kernel_launch(void* const* d_in, const int* in_sizes, int n_in,
                              void* d_out, int out_size)
{
    const float* feat   = (const float*)d_in[0];
    const int*   label  = (const int*)d_in[1];
    const float* anchor = (const float*)d_in[2];
    float* out = (float*)d_out;

    anchor_loss_main<<<MAIN_BLOCKS + NV, 512>>>(feat, label, anchor, out);
    anchor_loss_finalize<<<1, 256>>>(out);
}